// round 2
// baseline (speedup 1.0000x reference)
#include <cuda_runtime.h>
#include <math.h>

// ---------------- problem constants ----------------
#define DM    512          // d_model
#define NH    8            // heads
#define DKH   64           // head dim
#define NL    6            // layers
#define FFD   2048         // ffn dim
#define ROWS  2048         // B*S = B*T = 4*512
#define VOCAB 32000

// ---------------- scratch (static device memory; no allocation) ----------------
__device__ float g_xenc[ROWS * DM];       // encoder hidden (becomes enc_out)
__device__ float g_xdec[ROWS * DM];       // decoder hidden
__device__ float g_qkv[3 * ROWS * DM];    // q | k | v
__device__ float g_att[ROWS * DM];        // attention output (pre-projection)
__device__ float g_prj[ROWS * DM];        // projection / ffn2 result
__device__ float g_ffb[ROWS * FFD];       // ffn hidden

// ---------------- helpers ----------------
__device__ __forceinline__ float blk_reduce(float v, float* red, int op /*0=sum,1=max*/) {
#pragma unroll
    for (int o = 16; o; o >>= 1) {
        float t = __shfl_xor_sync(0xffffffffu, v, o);
        v = op ? fmaxf(v, t) : v + t;
    }
    int wid = threadIdx.x >> 5, lane = threadIdx.x & 31;
    int nw = blockDim.x >> 5;
    if (lane == 0) red[wid] = v;
    __syncthreads();
    if (wid == 0) {
        v = (lane < nw) ? red[lane] : (op ? -3.0e38f : 0.0f);
#pragma unroll
        for (int o = 4; o; o >>= 1) {
            float t = __shfl_xor_sync(0xffffffffu, v, o);
            v = op ? fmaxf(v, t) : v + t;
        }
        if (lane == 0) red[0] = v;
    }
    __syncthreads();
    float r = red[0];
    __syncthreads();
    return r;
}

// ---------------- embedding + positional encoding ----------------
// out[row, d] = emb[token[row], d] * sqrt(512) + PE(t, d), t = row % 512.
// PE computed in double: --use_fast_math would degrade sinf at args up to 511.
__global__ void embed_kernel(const int* __restrict__ tok, const float* __restrict__ emb,
                             float* __restrict__ out) {
    int i = blockIdx.x * 256 + threadIdx.x;   // over ROWS*DM
    int row = i >> 9, d = i & 511;
    int t = row & 511;
    int token = tok[row];
    int j = d & ~1;
    double ang = (double)t * pow(512.0, -(double)j / 512.0);
    float pe = (d & 1) ? (float)cos(ang) : (float)sin(ang);
    out[i] = emb[(size_t)token * DM + d] * 22.62741699796952f + pe;
}

// ---------------- SGEMM: C = A[M,K] @ W[K,N] + bias[N] (opt ReLU) ----------------
// 128x128 block tile, BK=8, 256 threads, 8x8 per thread split 4+4. z-batched on W/bias/C.
__global__ void __launch_bounds__(256) sgemm_kernel(
    const float* __restrict__ A, const float* __restrict__ W,
    const float* __restrict__ bias, float* __restrict__ C,
    int M, int N, int K, int relu,
    long long sW, long long sB, long long sC)
{
    W    += (long long)blockIdx.z * sW;
    bias += (long long)blockIdx.z * sB;
    C    += (long long)blockIdx.z * sC;

    __shared__ float As[8][128];
    __shared__ float Ws[8][128];

    const int tid = threadIdx.x;
    const int bm = blockIdx.y * 128;
    const int bn = blockIdx.x * 128;

    const int arow = tid >> 1, acol = (tid & 1) * 4;   // A loads: 128 rows x 8 k
    const int wrow = tid >> 5, wcol = (tid & 31) * 4;  // W loads: 8 k x 128 n
    const int tx = tid & 15, ty = tid >> 4;            // 16x16 thread grid

    float acc[8][8];
#pragma unroll
    for (int i = 0; i < 8; i++)
#pragma unroll
        for (int j = 0; j < 8; j++) acc[i][j] = 0.0f;

    const float* Aptr = A + (size_t)(bm + arow) * K + acol;
    const float* Wptr = W + (size_t)wrow * N + bn + wcol;

    for (int k0 = 0; k0 < K; k0 += 8) {
        float4 a4 = *(const float4*)Aptr;  Aptr += 8;
        float4 w4 = *(const float4*)Wptr;  Wptr += (size_t)8 * N;
        As[acol + 0][arow] = a4.x;
        As[acol + 1][arow] = a4.y;
        As[acol + 2][arow] = a4.z;
        As[acol + 3][arow] = a4.w;
        *(float4*)&Ws[wrow][wcol] = w4;
        __syncthreads();
#pragma unroll
        for (int kk = 0; kk < 8; kk++) {
            float4 a0 = *(const float4*)&As[kk][ty * 4];
            float4 a1 = *(const float4*)&As[kk][64 + ty * 4];
            float4 w0 = *(const float4*)&Ws[kk][tx * 4];
            float4 w1 = *(const float4*)&Ws[kk][64 + tx * 4];
            float a[8] = {a0.x, a0.y, a0.z, a0.w, a1.x, a1.y, a1.z, a1.w};
            float w[8] = {w0.x, w0.y, w0.z, w0.w, w1.x, w1.y, w1.z, w1.w};
#pragma unroll
            for (int i = 0; i < 8; i++)
#pragma unroll
                for (int j = 0; j < 8; j++) acc[i][j] += a[i] * w[j];
        }
        __syncthreads();
    }

    const float* bp = bias + bn;
#pragma unroll
    for (int ih = 0; ih < 2; ih++) {
#pragma unroll
        for (int i = 0; i < 4; i++) {
            int row = bm + ih * 64 + ty * 4 + i;
            float* crow = C + (size_t)row * N + bn;
#pragma unroll
            for (int jh = 0; jh < 2; jh++) {
                int col = jh * 64 + tx * 4;
                float4 o;
                o.x = acc[ih * 4 + i][jh * 4 + 0] + bp[col + 0];
                o.y = acc[ih * 4 + i][jh * 4 + 1] + bp[col + 1];
                o.z = acc[ih * 4 + i][jh * 4 + 2] + bp[col + 2];
                o.w = acc[ih * 4 + i][jh * 4 + 3] + bp[col + 3];
                if (relu) {
                    o.x = fmaxf(o.x, 0.0f); o.y = fmaxf(o.y, 0.0f);
                    o.z = fmaxf(o.z, 0.0f); o.w = fmaxf(o.w, 0.0f);
                }
                *(float4*)(crow + col) = o;
            }
        }
    }
}

// ---------------- fused attention: one CTA per (b, h, t) ----------------
// scores = q.k/8 (+mask), softmax over Skv, out = probs @ V   (Skv = 512)
// mask is int32 (bool coerced by harness); nonzero test also covers float32 coercion.
__global__ void __launch_bounds__(256) attn_kernel(
    const float* __restrict__ Q, const float* __restrict__ K,
    const float* __restrict__ V, const int* __restrict__ mask,
    float* __restrict__ O, int Tq, int Skv)
{
    const int t = blockIdx.x, h = blockIdx.y, b = blockIdx.z;
    const int tid = threadIdx.x;
    __shared__ float qs[DKH];
    __shared__ float sc[512];
    __shared__ float red[32];
    __shared__ float pv[4][DKH];

    const float* qrow = Q + ((size_t)(b * Tq + t)) * DM + h * DKH;
    if (tid < 16) ((float4*)qs)[tid] = ((const float4*)qrow)[tid];
    __syncthreads();

    const int* mrow = mask + ((size_t)(b * Tq + t)) * Skv;
    float lmax = -3.0e38f;
    for (int s = tid; s < Skv; s += 256) {
        const float4* krow = (const float4*)(K + ((size_t)(b * Skv + s)) * DM + h * DKH);
        float acc = 0.0f;
#pragma unroll
        for (int i = 0; i < 16; i++) {
            float4 k4 = krow[i];
            float4 q4 = ((float4*)qs)[i];
            acc += q4.x * k4.x + q4.y * k4.y + q4.z * k4.z + q4.w * k4.w;
        }
        acc *= 0.125f;                     // 1/sqrt(64)
        if (mrow[s] == 0) acc = -1.0e30f;  // masked -> effectively -inf
        sc[s] = acc;
        lmax = fmaxf(lmax, acc);
    }
    float mx = blk_reduce(lmax, red, 1);

    float lsum = 0.0f;
    for (int s = tid; s < Skv; s += 256) {
        float p = __expf(sc[s] - mx);
        sc[s] = p;
        lsum += p;
    }
    float sum = blk_reduce(lsum, red, 0);
    float inv = 1.0f / sum;

    // probs @ V: thread (c,d), c = tid>>6 chunks over s, d = tid&63 dims (coalesced V reads)
    int d = tid & 63, c = tid >> 6;
    int chunk = Skv >> 2;
    float acc = 0.0f;
    const float* vbase = V + ((size_t)b * Skv) * DM + h * DKH + d;
    for (int s = c * chunk; s < (c + 1) * chunk; s++)
        acc += sc[s] * vbase[(size_t)s * DM];
    pv[c][d] = acc;
    __syncthreads();
    if (tid < 64) {
        float o = (pv[0][tid] + pv[1][tid] + pv[2][tid] + pv[3][tid]) * inv;
        O[((size_t)(b * Tq + t)) * DM + h * DKH + tid] = o;
    }
}

// ---------------- fused residual add + LayerNorm ----------------
// out[row] = LN(x[row] + y[row]) * g + b ; one CTA of 128 threads per row (D=512)
__global__ void __launch_bounds__(128) add_ln_kernel(
    const float* __restrict__ x, const float* __restrict__ y,
    const float* __restrict__ g, const float* __restrict__ bb,
    float* __restrict__ out)
{
    __shared__ float red[32];
    const int row = blockIdx.x, tid = threadIdx.x;
    const float4 xv = ((const float4*)(x + (size_t)row * DM))[tid];
    const float4 yv = ((const float4*)(y + (size_t)row * DM))[tid];
    float4 v;
    v.x = xv.x + yv.x; v.y = xv.y + yv.y; v.z = xv.z + yv.z; v.w = xv.w + yv.w;
    float s  = v.x + v.y + v.z + v.w;
    float sq = v.x * v.x + v.y * v.y + v.z * v.z + v.w * v.w;
    float S  = blk_reduce(s,  red, 0);
    float SQ = blk_reduce(sq, red, 0);
    float mu = S * (1.0f / DM);
    float var = SQ * (1.0f / DM) - mu * mu;
    float r = rsqrtf(var + 1e-5f);
    const float4 g4 = ((const float4*)g)[tid];
    const float4 b4 = ((const float4*)bb)[tid];
    float4 o;
    o.x = (v.x - mu) * r * g4.x + b4.x;
    o.y = (v.y - mu) * r * g4.y + b4.y;
    o.z = (v.z - mu) * r * g4.z + b4.z;
    o.w = (v.w - mu) * r * g4.w + b4.w;
    ((float4*)(out + (size_t)row * DM))[tid] = o;
}

// ---------------- host orchestration ----------------
static inline void launch_gemm(const float* A, const float* W, const float* b, float* C,
                               int M, int N, int K, int relu,
                               int batch = 1, long long sW = 0, long long sB = 0, long long sC = 0) {
    dim3 grid(N / 128, M / 128, batch);
    sgemm_kernel<<<grid, 256>>>(A, W, b, C, M, N, K, relu, sW, sB, sC);
}

extern "C" void kernel_launch(void* const* d_in, const int* in_sizes, int n_in,
                              void* d_out, int out_size) {
    (void)in_sizes; (void)n_in; (void)out_size;
    const int* enc_tok  = (const int*)d_in[0];
    const int* dec_tok  = (const int*)d_in[1];
    const int* m_enc    = (const int*)d_in[2];
    const int* m_dec    = (const int*)d_in[3];
    const int* m_cross  = (const int*)d_in[4];
    const float* enc_emb = (const float*)d_in[5];
    const float* dec_emb = (const float*)d_in[6];
    const float* e_qkvw  = (const float*)d_in[7];
    const float* e_qkvb  = (const float*)d_in[8];
    const float* e_w1    = (const float*)d_in[9];
    const float* e_b1    = (const float*)d_in[10];
    const float* e_w2    = (const float*)d_in[11];
    const float* e_b2    = (const float*)d_in[12];
    const float* e_lng   = (const float*)d_in[13];
    const float* e_lnb   = (const float*)d_in[14];
    const float* ds_qkvw = (const float*)d_in[15];
    const float* ds_qkvb = (const float*)d_in[16];
    const float* dc_qkvw = (const float*)d_in[17];
    const float* dc_qkvb = (const float*)d_in[18];
    const float* d_w1    = (const float*)d_in[19];
    const float* d_b1    = (const float*)d_in[20];
    const float* d_w2    = (const float*)d_in[21];
    const float* d_b2    = (const float*)d_in[22];
    const float* d_lng   = (const float*)d_in[23];
    const float* d_lnb   = (const float*)d_in[24];
    const float* out_w   = (const float*)d_in[25];
    const float* out_b   = (const float*)d_in[26];
    float* out = (float*)d_out;

    float *xenc, *xdec, *qkv, *att, *prj, *ffb;
    cudaGetSymbolAddress((void**)&xenc, g_xenc);
    cudaGetSymbolAddress((void**)&xdec, g_xdec);
    cudaGetSymbolAddress((void**)&qkv,  g_qkv);
    cudaGetSymbolAddress((void**)&att,  g_att);
    cudaGetSymbolAddress((void**)&prj,  g_prj);
    cudaGetSymbolAddress((void**)&ffb,  g_ffb);
    float* q = qkv;
    float* k = qkv + (size_t)ROWS * DM;
    float* v = qkv + 2 * (size_t)ROWS * DM;

    const long long sW = (long long)DM * DM;
    const long long sB = DM;
    const long long sC = (long long)ROWS * DM;

    // embeddings + positional encoding
    embed_kernel<<<(ROWS * DM) / 256, 256>>>(enc_tok, enc_emb, xenc);
    embed_kernel<<<(ROWS * DM) / 256, 256>>>(dec_tok, dec_emb, xdec);

    // ---------------- encoder ----------------
    for (int i = 0; i < NL; i++) {
        const float* Wl = e_qkvw + (size_t)i * 4 * sW;
        const float* Bl = e_qkvb + (size_t)i * 4 * DM;
        launch_gemm(xenc, Wl, Bl, qkv, ROWS, DM, DM, 0, 3, sW, sB, sC);       // Q,K,V batched
        attn_kernel<<<dim3(512, NH, 4), 256>>>(q, k, v, m_enc, att, 512, 512);
        launch_gemm(att, Wl + 3 * sW, Bl + 3 * DM, prj, ROWS, DM, DM, 0);     // O proj
        add_ln_kernel<<<ROWS, 128>>>(xenc, prj,
                                     e_lng + (size_t)(i * 2) * DM, e_lnb + (size_t)(i * 2) * DM, xenc);
        launch_gemm(xenc, e_w1 + (size_t)i * DM * FFD, e_b1 + (size_t)i * FFD, ffb, ROWS, FFD, DM, 1);
        launch_gemm(ffb,  e_w2 + (size_t)i * FFD * DM, e_b2 + (size_t)i * DM,  prj, ROWS, DM, FFD, 0);
        add_ln_kernel<<<ROWS, 128>>>(xenc, prj,
                                     e_lng + (size_t)(i * 2 + 1) * DM, e_lnb + (size_t)(i * 2 + 1) * DM, xenc);
    }

    // ---------------- decoder ----------------
    for (int i = 0; i < NL; i++) {
        // self-attention
        const float* Wl = ds_qkvw + (size_t)i * 4 * sW;
        const float* Bl = ds_qkvb + (size_t)i * 4 * DM;
        launch_gemm(xdec, Wl, Bl, qkv, ROWS, DM, DM, 0, 3, sW, sB, sC);
        attn_kernel<<<dim3(512, NH, 4), 256>>>(q, k, v, m_dec, att, 512, 512);
        launch_gemm(att, Wl + 3 * sW, Bl + 3 * DM, prj, ROWS, DM, DM, 0);
        add_ln_kernel<<<ROWS, 128>>>(xdec, prj,
                                     d_lng + (size_t)(i * 3) * DM, d_lnb + (size_t)(i * 3) * DM, xdec);
        // cross-attention: q from decoder, k/v from encoder output
        const float* Wc = dc_qkvw + (size_t)i * 4 * sW;
        const float* Bc = dc_qkvb + (size_t)i * 4 * DM;
        launch_gemm(xdec, Wc, Bc, q, ROWS, DM, DM, 0);                          // Q
        launch_gemm(xenc, Wc + sW, Bc + DM, k, ROWS, DM, DM, 0, 2, sW, sB, sC); // K,V batched (v = k + sC)
        attn_kernel<<<dim3(512, NH, 4), 256>>>(q, k, v, m_cross, att, 512, 512);
        launch_gemm(att, Wc + 3 * sW, Bc + 3 * DM, prj, ROWS, DM, DM, 0);
        add_ln_kernel<<<ROWS, 128>>>(xdec, prj,
                                     d_lng + (size_t)(i * 3 + 1) * DM, d_lnb + (size_t)(i * 3 + 1) * DM, xdec);
        // feed-forward
        launch_gemm(xdec, d_w1 + (size_t)i * DM * FFD, d_b1 + (size_t)i * FFD, ffb, ROWS, FFD, DM, 1);
        launch_gemm(ffb,  d_w2 + (size_t)i * FFD * DM, d_b2 + (size_t)i * DM,  prj, ROWS, DM, FFD, 0);
        add_ln_kernel<<<ROWS, 128>>>(xdec, prj,
                                     d_lng + (size_t)(i * 3 + 2) * DM, d_lnb + (size_t)(i * 3 + 2) * DM, xdec);
    }

    // final vocab projection straight into d_out
    launch_gemm(xdec, out_w, out_b, out, ROWS, VOCAB, DM, 0);
}

// round 4
// speedup vs baseline: 1.3741x; 1.3741x over previous
#include <cuda_runtime.h>
#include <cuda_bf16.h>
#include <math.h>
#include <stdint.h>

// ---------------- problem constants ----------------
#define DM    512
#define NH    8
#define DKH   64
#define NL    6
#define FFD   2048
#define ROWS  2048
#define VOCAB 32000

// ---------------- scratch ----------------
__device__ float g_xenc[ROWS * DM];
__device__ float g_xdec[ROWS * DM];
__device__ float g_qkv[3 * ROWS * DM];
__device__ float g_att[ROWS * DM];
__device__ float g_prj[ROWS * DM];
__device__ float g_ffb[ROWS * FFD];

// prepped weights: bf16 hi/lo, [N][K] K-major layout
#define OFF_ENC_QKVO 0LL
#define OFF_DS_QKVO  6291456LL
#define OFF_DC_QKVO  12582912LL
#define OFF_ENC_W1   18874368LL
#define OFF_ENC_W2   25165824LL
#define OFF_DEC_W1   31457280LL
#define OFF_DEC_W2   37748736LL
#define OFF_VOCAB    44040192LL
#define W_TOTAL      60424192LL
__device__ __nv_bfloat16 g_whi[W_TOTAL];
__device__ __nv_bfloat16 g_wlo[W_TOTAL];

// ---------------- low-level helpers (baseline PTX only: sm_80+ features) ----------------
__device__ __forceinline__ uint32_t smem_to_u32(const void* p) {
    uint32_t a;
    asm("{ .reg .u64 t; cvta.to.shared.u64 t, %1; cvt.u32.u64 %0, t; }" : "=r"(a) : "l"(p));
    return a;
}
#define STS64(smem_addr, val) \
    asm volatile("st.shared.b64 [%0], %1;" :: "r"(smem_addr), "l"(val) : "memory")
#define CP_ASYNC16(dst, src) \
    asm volatile("cp.async.cg.shared.global [%0], [%1], 16;" :: "r"(dst), "l"(src) : "memory")
#define CP_COMMIT asm volatile("cp.async.commit_group;" ::: "memory")
#define CP_WAIT0  asm volatile("cp.async.wait_group 0;" ::: "memory")

__device__ __forceinline__ void ldsm_x4(uint32_t* r, uint32_t addr) {
    asm volatile("ldmatrix.sync.aligned.m8n8.x4.shared.b16 {%0,%1,%2,%3}, [%4];"
        : "=r"(r[0]), "=r"(r[1]), "=r"(r[2]), "=r"(r[3]) : "r"(addr));
}
__device__ __forceinline__ void mma_bf16(float* d, const uint32_t* a, const uint32_t* b) {
    asm volatile("mma.sync.aligned.m16n8k16.row.col.f32.bf16.bf16.f32 "
        "{%0,%1,%2,%3}, {%4,%5,%6,%7}, {%8,%9}, {%0,%1,%2,%3};"
        : "+f"(d[0]), "+f"(d[1]), "+f"(d[2]), "+f"(d[3])
        : "r"(a[0]), "r"(a[1]), "r"(a[2]), "r"(a[3]), "r"(b[0]), "r"(b[1]));
}
__device__ __forceinline__ unsigned long long pack4bf(__nv_bfloat16 a, __nv_bfloat16 b,
                                                      __nv_bfloat16 c, __nv_bfloat16 d) {
    union { __nv_bfloat16 h[4]; unsigned long long u; } x;
    x.h[0] = a; x.h[1] = b; x.h[2] = c; x.h[3] = d;
    return x.u;
}

// ---------------- weight prep: fp32 [K][N] -> bf16 hi/lo [N][K] ----------------
__global__ void __launch_bounds__(256) prep_w(const float* __restrict__ W,
                                              __nv_bfloat16* __restrict__ hi,
                                              __nv_bfloat16* __restrict__ lo,
                                              int K, int N, long long sIn, long long sOut) {
    W  += (long long)blockIdx.z * sIn;
    hi += (long long)blockIdx.z * sOut;
    lo += (long long)blockIdx.z * sOut;
    __shared__ float t[32][33];
    const int n0 = blockIdx.x * 32, k0 = blockIdx.y * 32;
    const int tx = threadIdx.x, ty = threadIdx.y;
#pragma unroll
    for (int j = 0; j < 32; j += 8)
        t[ty + j][tx] = W[(size_t)(k0 + ty + j) * N + n0 + tx];
    __syncthreads();
#pragma unroll
    for (int j = 0; j < 32; j += 8) {
        float v = t[tx][ty + j];
        __nv_bfloat16 h = __float2bfloat16(v);
        __nv_bfloat16 l = __float2bfloat16(v - __bfloat162float(h));
        size_t o = (size_t)(n0 + ty + j) * K + k0 + tx;
        hi[o] = h; lo[o] = l;
    }
}

// ---------------- mma.sync GEMM: C[M,N] = A[M,K](fp32) @ W[N,K](bf16 hi/lo)^T + bias ----------------
// 128x128 CTA tile, 8 warps (4x2), warp tile 32x64, K-chunks of 32, double-buffered smem.
// 3xBF16 compensation: acc += Ahi*Bhi + Ahi*Blo + Alo*Bhi (fp32 accum).
#define KC 32
#define LDSB 80              // smem row stride in bytes (40 bf16) -> conflict-free ldmatrix
#define AH_OFF 0
#define AL_OFF 10240
#define BH_OFF 20480
#define BL_OFF 30720
#define STAGE_B 40960
#define HG_SMEM (2 * STAGE_B)

__device__ __forceinline__ void stA_stage(uint32_t stage, uint32_t aDstBase, const float4* aPre) {
#pragma unroll
    for (int q = 0; q < 4; q++) {
        float4 v = aPre[q];
        __nv_bfloat16 h0 = __float2bfloat16(v.x), h1 = __float2bfloat16(v.y);
        __nv_bfloat16 h2 = __float2bfloat16(v.z), h3 = __float2bfloat16(v.w);
        __nv_bfloat16 l0 = __float2bfloat16(v.x - __bfloat162float(h0));
        __nv_bfloat16 l1 = __float2bfloat16(v.y - __bfloat162float(h1));
        __nv_bfloat16 l2 = __float2bfloat16(v.z - __bfloat162float(h2));
        __nv_bfloat16 l3 = __float2bfloat16(v.w - __bfloat162float(h3));
        STS64(stage + AH_OFF + aDstBase + q * 8, pack4bf(h0, h1, h2, h3));
        STS64(stage + AL_OFF + aDstBase + q * 8, pack4bf(l0, l1, l2, l3));
    }
}

__global__ void __launch_bounds__(256) hgemm(
    const float* __restrict__ A, const __nv_bfloat16* __restrict__ Whi,
    const __nv_bfloat16* __restrict__ Wlo, const float* __restrict__ bias,
    float* __restrict__ C, int M, int N, int K, int relu,
    long long sA, long long sW, long long sB, long long sC)
{
    extern __shared__ char sm[];
    A    += (long long)blockIdx.z * sA;
    Whi  += (long long)blockIdx.z * sW;
    Wlo  += (long long)blockIdx.z * sW;
    bias += (long long)blockIdx.z * sB;
    C    += (long long)blockIdx.z * sC;

    const int tid = threadIdx.x, lane = tid & 31, wid = tid >> 5;
    const int wy = wid & 3, wx = wid >> 2;
    const int bm = blockIdx.y * 128, bn = blockIdx.x * 128;
    const uint32_t sbase = smem_to_u32(sm);

    float acc[2][8][4];
#pragma unroll
    for (int f = 0; f < 2; f++)
#pragma unroll
        for (int g = 0; g < 8; g++)
#pragma unroll
            for (int r = 0; r < 4; r++) acc[f][g][r] = 0.0f;

    // A prefetch mapping: thread -> row (tid>>1), half (tid&1)*16 floats
    const int arow = tid >> 1, ahalf = tid & 1;
    const float* aSrc = A + (size_t)(bm + arow) * K + ahalf * 16;
    const uint32_t aDstBase = (uint32_t)(arow * LDSB + ahalf * 32);

    float4 aPre[4];
    // ---- prologue: chunk 0 ----
#pragma unroll
    for (int q = 0; q < 4; q++) aPre[q] = *(const float4*)(aSrc + q * 4);
#pragma unroll
    for (int j = 0; j < 2; j++) {
        int idx = tid + 256 * j;
        int row = idx >> 2, c16 = idx & 3;
        size_t go = (size_t)(bn + row) * K;
        uint32_t d = (uint32_t)(row * LDSB + c16 * 16);
        CP_ASYNC16(sbase + BH_OFF + d, (const char*)(Whi + go) + c16 * 16);
        CP_ASYNC16(sbase + BL_OFF + d, (const char*)(Wlo + go) + c16 * 16);
    }
    CP_COMMIT;
    stA_stage(sbase, aDstBase, aPre);
    CP_WAIT0;
    __syncthreads();

    const int nch = K / KC;
    for (int c = 0; c < nch; ++c) {
        const uint32_t st  = sbase + (uint32_t)(c & 1) * STAGE_B;
        const uint32_t stN = sbase + (uint32_t)((c + 1) & 1) * STAGE_B;
        const bool more = (c + 1) < nch;
        if (more) {
            const float* as = aSrc + (c + 1) * KC;
#pragma unroll
            for (int q = 0; q < 4; q++) aPre[q] = *(const float4*)(as + q * 4);
#pragma unroll
            for (int j = 0; j < 2; j++) {
                int idx = tid + 256 * j;
                int row = idx >> 2, c16 = idx & 3;
                size_t go = (size_t)(bn + row) * K + (size_t)(c + 1) * KC;
                uint32_t d = (uint32_t)(row * LDSB + c16 * 16);
                CP_ASYNC16(stN + BH_OFF + d, (const char*)(Whi + go) + c16 * 16);
                CP_ASYNC16(stN + BL_OFF + d, (const char*)(Wlo + go) + c16 * 16);
            }
            CP_COMMIT;
        }
        // ---- MMA on current stage (2 k16 steps) ----
#pragma unroll
        for (int ks = 0; ks < 2; ++ks) {
            uint32_t ah[2][4], al[2][4];
            const int aRow0 = wy * 32 + (lane & 7) + ((lane >> 3) & 1) * 8;
            const int aKb = (ks * 16 + ((lane >> 4) & 1) * 8) * 2;
#pragma unroll
            for (int f = 0; f < 2; ++f) {
                uint32_t ad = st + AH_OFF + (uint32_t)((aRow0 + f * 16) * LDSB + aKb);
                ldsm_x4(ah[f], ad);
                ldsm_x4(al[f], ad + (AL_OFF - AH_OFF));
            }
            const int bRow0 = wx * 64 + (lane & 7) + ((lane >> 4) & 1) * 8;
            const int bKb = (ks * 16 + ((lane >> 3) & 1) * 8) * 2;
#pragma unroll
            for (int gp = 0; gp < 4; ++gp) {
                uint32_t bh[4], bl[4];
                uint32_t bd = st + BH_OFF + (uint32_t)((bRow0 + gp * 16) * LDSB + bKb);
                ldsm_x4(bh, bd);
                ldsm_x4(bl, bd + (BL_OFF - BH_OFF));
#pragma unroll
                for (int f = 0; f < 2; ++f) {
                    mma_bf16(acc[f][gp * 2 + 0], ah[f], bh + 0);
                    mma_bf16(acc[f][gp * 2 + 1], ah[f], bh + 2);
                    mma_bf16(acc[f][gp * 2 + 0], ah[f], bl + 0);
                    mma_bf16(acc[f][gp * 2 + 1], ah[f], bl + 2);
                    mma_bf16(acc[f][gp * 2 + 0], al[f], bh + 0);
                    mma_bf16(acc[f][gp * 2 + 1], al[f], bh + 2);
                }
            }
        }
        if (more) {
            stA_stage(stN, aDstBase, aPre);
            CP_WAIT0;
        }
        __syncthreads();
    }

    // ---- epilogue: bias (+relu), fp32 stores ----
    const int mBase = bm + wy * 32 + (lane >> 2);
    const int nBase = bn + wx * 64 + (lane & 3) * 2;
#pragma unroll
    for (int f = 0; f < 2; ++f) {
        const int r0 = mBase + f * 16;
#pragma unroll
        for (int g = 0; g < 8; ++g) {
            const int col = nBase + g * 8;
            const float bx = bias[col], by = bias[col + 1];
            float2 v0, v1;
            v0.x = acc[f][g][0] + bx; v0.y = acc[f][g][1] + by;
            v1.x = acc[f][g][2] + bx; v1.y = acc[f][g][3] + by;
            if (relu) {
                v0.x = fmaxf(v0.x, 0.0f); v0.y = fmaxf(v0.y, 0.0f);
                v1.x = fmaxf(v1.x, 0.0f); v1.y = fmaxf(v1.y, 0.0f);
            }
            *(float2*)(C + (size_t)r0 * N + col) = v0;
            *(float2*)(C + (size_t)(r0 + 8) * N + col) = v1;
        }
    }
}

// ---------------- reduce helper ----------------
__device__ __forceinline__ float blk_reduce(float v, float* red, int op) {
#pragma unroll
    for (int o = 16; o; o >>= 1) {
        float t = __shfl_xor_sync(0xffffffffu, v, o);
        v = op ? fmaxf(v, t) : v + t;
    }
    int wid = threadIdx.x >> 5, lane = threadIdx.x & 31;
    int nw = blockDim.x >> 5;
    if (lane == 0) red[wid] = v;
    __syncthreads();
    if (wid == 0) {
        v = (lane < nw) ? red[lane] : (op ? -3.0e38f : 0.0f);
#pragma unroll
        for (int o = 4; o; o >>= 1) {
            float t = __shfl_xor_sync(0xffffffffu, v, o);
            v = op ? fmaxf(v, t) : v + t;
        }
        if (lane == 0) red[0] = v;
    }
    __syncthreads();
    float r = red[0];
    __syncthreads();
    return r;
}

// ---------------- embedding + positional encoding ----------------
__global__ void embed_kernel(const int* __restrict__ tok, const float* __restrict__ emb,
                             float* __restrict__ out) {
    int i = blockIdx.x * 256 + threadIdx.x;
    int row = i >> 9, d = i & 511;
    int t = row & 511;
    int token = tok[row];
    int j = d & ~1;
    double ang = (double)t * pow(512.0, -(double)j / 512.0);
    float pe = (d & 1) ? (float)cos(ang) : (float)sin(ang);
    out[i] = emb[(size_t)token * DM + d] * 22.62741699796952f + pe;
}

// ---------------- fused attention ----------------
__global__ void __launch_bounds__(256) attn_kernel(
    const float* __restrict__ Q, const float* __restrict__ K,
    const float* __restrict__ V, const int* __restrict__ mask,
    float* __restrict__ O, int Tq, int Skv) {
    const int t = blockIdx.x, h = blockIdx.y, b = blockIdx.z;
    const int tid = threadIdx.x;
    __shared__ float qs[DKH];
    __shared__ float sc[512];
    __shared__ float red[32];
    __shared__ float pv[4][DKH];

    const float* qrow = Q + ((size_t)(b * Tq + t)) * DM + h * DKH;
    if (tid < 16) ((float4*)qs)[tid] = ((const float4*)qrow)[tid];
    __syncthreads();

    const int* mrow = mask + ((size_t)(b * Tq + t)) * Skv;
    float lmax = -3.0e38f;
    for (int s = tid; s < Skv; s += 256) {
        const float4* krow = (const float4*)(K + ((size_t)(b * Skv + s)) * DM + h * DKH);
        float acc = 0.0f;
#pragma unroll
        for (int i = 0; i < 16; i++) {
            float4 k4 = krow[i];
            float4 q4 = ((float4*)qs)[i];
            acc += q4.x * k4.x + q4.y * k4.y + q4.z * k4.z + q4.w * k4.w;
        }
        acc *= 0.125f;
        if (mrow[s] == 0) acc = -1.0e30f;
        sc[s] = acc;
        lmax = fmaxf(lmax, acc);
    }
    float mx = blk_reduce(lmax, red, 1);

    float lsum = 0.0f;
    for (int s = tid; s < Skv; s += 256) {
        float p = __expf(sc[s] - mx);
        sc[s] = p;
        lsum += p;
    }
    float sum = blk_reduce(lsum, red, 0);
    float inv = 1.0f / sum;

    int d = tid & 63, c = tid >> 6;
    int chunk = Skv >> 2;
    float acc = 0.0f;
    const float* vbase = V + ((size_t)b * Skv) * DM + h * DKH + d;
    for (int s = c * chunk; s < (c + 1) * chunk; s++)
        acc += sc[s] * vbase[(size_t)s * DM];
    pv[c][d] = acc;
    __syncthreads();
    if (tid < 64) {
        float o = (pv[0][tid] + pv[1][tid] + pv[2][tid] + pv[3][tid]) * inv;
        O[((size_t)(b * Tq + t)) * DM + h * DKH + tid] = o;
    }
}

// ---------------- fused residual add + LayerNorm ----------------
__global__ void __launch_bounds__(128) add_ln_kernel(
    const float* __restrict__ x, const float* __restrict__ y,
    const float* __restrict__ g, const float* __restrict__ bb,
    float* __restrict__ out) {
    __shared__ float red[32];
    const int row = blockIdx.x, tid = threadIdx.x;
    const float4 xv = ((const float4*)(x + (size_t)row * DM))[tid];
    const float4 yv = ((const float4*)(y + (size_t)row * DM))[tid];
    float4 v;
    v.x = xv.x + yv.x; v.y = xv.y + yv.y; v.z = xv.z + yv.z; v.w = xv.w + yv.w;
    float s  = v.x + v.y + v.z + v.w;
    float sq = v.x * v.x + v.y * v.y + v.z * v.z + v.w * v.w;
    float S  = blk_reduce(s,  red, 0);
    float SQ = blk_reduce(sq, red, 0);
    float mu = S * (1.0f / DM);
    float var = SQ * (1.0f / DM) - mu * mu;
    float r = rsqrtf(var + 1e-5f);
    const float4 g4 = ((const float4*)g)[tid];
    const float4 b4 = ((const float4*)bb)[tid];
    float4 o;
    o.x = (v.x - mu) * r * g4.x + b4.x;
    o.y = (v.y - mu) * r * g4.y + b4.y;
    o.z = (v.z - mu) * r * g4.z + b4.z;
    o.w = (v.w - mu) * r * g4.w + b4.w;
    ((float4*)(out + (size_t)row * DM))[tid] = o;
}

// ---------------- host orchestration ----------------
static __nv_bfloat16 *h_whi, *h_wlo;

static inline void tcg(const float* A, long long wOff, const float* b, float* C,
                       int M, int N, int K, int relu,
                       int batch = 1, long long sA = 0, long long sW = 0,
                       long long sB = 0, long long sC = 0) {
    dim3 grid(N / 128, M / 128, batch);
    hgemm<<<grid, 256, HG_SMEM>>>(A, h_whi + wOff, h_wlo + wOff, b, C,
                                  M, N, K, relu, sA, sW, sB, sC);
}

extern "C" void kernel_launch(void* const* d_in, const int* in_sizes, int n_in,
                              void* d_out, int out_size) {
    (void)in_sizes; (void)n_in; (void)out_size;
    const int* enc_tok  = (const int*)d_in[0];
    const int* dec_tok  = (const int*)d_in[1];
    const int* m_enc    = (const int*)d_in[2];
    const int* m_dec    = (const int*)d_in[3];
    const int* m_cross  = (const int*)d_in[4];
    const float* enc_emb = (const float*)d_in[5];
    const float* dec_emb = (const float*)d_in[6];
    const float* e_qkvw  = (const float*)d_in[7];
    const float* e_qkvb  = (const float*)d_in[8];
    const float* e_w1    = (const float*)d_in[9];
    const float* e_b1    = (const float*)d_in[10];
    const float* e_w2    = (const float*)d_in[11];
    const float* e_b2    = (const float*)d_in[12];
    const float* e_lng   = (const float*)d_in[13];
    const float* e_lnb   = (const float*)d_in[14];
    const float* ds_qkvw = (const float*)d_in[15];
    const float* ds_qkvb = (const float*)d_in[16];
    const float* dc_qkvw = (const float*)d_in[17];
    const float* dc_qkvb = (const float*)d_in[18];
    const float* d_w1    = (const float*)d_in[19];
    const float* d_b1    = (const float*)d_in[20];
    const float* d_w2    = (const float*)d_in[21];
    const float* d_b2    = (const float*)d_in[22];
    const float* d_lng   = (const float*)d_in[23];
    const float* d_lnb   = (const float*)d_in[24];
    const float* out_w   = (const float*)d_in[25];
    const float* out_b   = (const float*)d_in[26];
    float* out = (float*)d_out;

    float *xenc, *xdec, *qkv, *att, *prj, *ffb;
    cudaGetSymbolAddress((void**)&xenc, g_xenc);
    cudaGetSymbolAddress((void**)&xdec, g_xdec);
    cudaGetSymbolAddress((void**)&qkv,  g_qkv);
    cudaGetSymbolAddress((void**)&att,  g_att);
    cudaGetSymbolAddress((void**)&prj,  g_prj);
    cudaGetSymbolAddress((void**)&ffb,  g_ffb);
    cudaGetSymbolAddress((void**)&h_whi, g_whi);
    cudaGetSymbolAddress((void**)&h_wlo, g_wlo);
    float* q = qkv;
    float* k = qkv + (size_t)ROWS * DM;
    float* v = qkv + 2 * (size_t)ROWS * DM;

    cudaFuncSetAttribute(hgemm, cudaFuncAttributeMaxDynamicSharedMemorySize, HG_SMEM);

    // ---- weight prep (fp32 [K][N] -> bf16 hi/lo [N][K]) ----
    dim3 pb(32, 8);
    prep_w<<<dim3(16, 16, 24), pb>>>(e_qkvw,  h_whi + OFF_ENC_QKVO, h_wlo + OFF_ENC_QKVO, 512, 512, 262144, 262144);
    prep_w<<<dim3(16, 16, 24), pb>>>(ds_qkvw, h_whi + OFF_DS_QKVO,  h_wlo + OFF_DS_QKVO,  512, 512, 262144, 262144);
    prep_w<<<dim3(16, 16, 24), pb>>>(dc_qkvw, h_whi + OFF_DC_QKVO,  h_wlo + OFF_DC_QKVO,  512, 512, 262144, 262144);
    prep_w<<<dim3(64, 16, 6),  pb>>>(e_w1, h_whi + OFF_ENC_W1, h_wlo + OFF_ENC_W1, 512, 2048, 1048576, 1048576);
    prep_w<<<dim3(16, 64, 6),  pb>>>(e_w2, h_whi + OFF_ENC_W2, h_wlo + OFF_ENC_W2, 2048, 512, 1048576, 1048576);
    prep_w<<<dim3(64, 16, 6),  pb>>>(d_w1, h_whi + OFF_DEC_W1, h_wlo + OFF_DEC_W1, 512, 2048, 1048576, 1048576);
    prep_w<<<dim3(16, 64, 6),  pb>>>(d_w2, h_whi + OFF_DEC_W2, h_wlo + OFF_DEC_W2, 2048, 512, 1048576, 1048576);
    prep_w<<<dim3(1000, 16, 1), pb>>>(out_w, h_whi + OFF_VOCAB, h_wlo + OFF_VOCAB, 512, 32000, 0, 0);

    embed_kernel<<<(ROWS * DM) / 256, 256>>>(enc_tok, enc_emb, xenc);
    embed_kernel<<<(ROWS * DM) / 256, 256>>>(dec_tok, dec_emb, xdec);

    const long long sWm = 262144, sBv = DM, sCv = (long long)ROWS * DM;

    // ---------------- encoder ----------------
    for (int i = 0; i < NL; i++) {
        long long qo = OFF_ENC_QKVO + (long long)i * 4 * sWm;
        const float* Bl = e_qkvb + (size_t)i * 4 * DM;
        tcg(xenc, qo, Bl, qkv, ROWS, DM, DM, 0, 3, 0, sWm, sBv, sCv);
        attn_kernel<<<dim3(512, NH, 4), 256>>>(q, k, v, m_enc, att, 512, 512);
        tcg(att, qo + 3 * sWm, Bl + 3 * DM, prj, ROWS, DM, DM, 0);
        add_ln_kernel<<<ROWS, 128>>>(xenc, prj, e_lng + (size_t)(i * 2) * DM, e_lnb + (size_t)(i * 2) * DM, xenc);
        tcg(xenc, OFF_ENC_W1 + (long long)i * 1048576, e_b1 + (size_t)i * FFD, ffb, ROWS, FFD, DM, 1);
        tcg(ffb,  OFF_ENC_W2 + (long long)i * 1048576, e_b2 + (size_t)i * DM,  prj, ROWS, DM, FFD, 0);
        add_ln_kernel<<<ROWS, 128>>>(xenc, prj, e_lng + (size_t)(i * 2 + 1) * DM, e_lnb + (size_t)(i * 2 + 1) * DM, xenc);
    }

    // ---------------- decoder ----------------
    for (int i = 0; i < NL; i++) {
        long long qo = OFF_DS_QKVO + (long long)i * 4 * sWm;
        const float* Bl = ds_qkvb + (size_t)i * 4 * DM;
        tcg(xdec, qo, Bl, qkv, ROWS, DM, DM, 0, 3, 0, sWm, sBv, sCv);
        attn_kernel<<<dim3(512, NH, 4), 256>>>(q, k, v, m_dec, att, 512, 512);
        tcg(att, qo + 3 * sWm, Bl + 3 * DM, prj, ROWS, DM, DM, 0);
        add_ln_kernel<<<ROWS, 128>>>(xdec, prj, d_lng + (size_t)(i * 3) * DM, d_lnb + (size_t)(i * 3) * DM, xdec);

        long long co = OFF_DC_QKVO + (long long)i * 4 * sWm;
        const float* Bc = dc_qkvb + (size_t)i * 4 * DM;
        tcg(xdec, co, Bc, q, ROWS, DM, DM, 0);
        tcg(xenc, co + sWm, Bc + DM, k, ROWS, DM, DM, 0, 2, 0, sWm, sBv, sCv);
        attn_kernel<<<dim3(512, NH, 4), 256>>>(q, k, v, m_cross, att, 512, 512);
        tcg(att, co + 3 * sWm, Bc + 3 * DM, prj, ROWS, DM, DM, 0);
        add_ln_kernel<<<ROWS, 128>>>(xdec, prj, d_lng + (size_t)(i * 3 + 1) * DM, d_lnb + (size_t)(i * 3 + 1) * DM, xdec);

        tcg(xdec, OFF_DEC_W1 + (long long)i * 1048576, d_b1 + (size_t)i * FFD, ffb, ROWS, FFD, DM, 1);
        tcg(ffb,  OFF_DEC_W2 + (long long)i * 1048576, d_b2 + (size_t)i * DM,  prj, ROWS, DM, FFD, 0);
        add_ln_kernel<<<ROWS, 128>>>(xdec, prj, d_lng + (size_t)(i * 3 + 2) * DM, d_lnb + (size_t)(i * 3 + 2) * DM, xdec);
    }

    // final vocab projection
    tcg(xdec, OFF_VOCAB, out_b, out, ROWS, VOCAB, DM, 0);
}